// round 17
// baseline (speedup 1.0000x reference)
#include <cuda_runtime.h>

#define BB 128
#define HH 256
#define WW 256
#define SHIFT 32
#define HW (HH*WW)      // 65536
#define CHW (3*HW)      // 196608
#define HW4 (HW/4)      // 16384 float4 per plane
#define RBLKS 64        // reduce units per image (12KB each)
#define BPI 64          // transform units per image (1024 px each)
#define HALF (BB/2)     // 64 images per half

__device__ float g_part[BB * RBLKS];

// ---- reduce unit: one block sums 1/64 of one image (768 float4, 3/thread) ----
__device__ __forceinline__ void reduce_unit(const float* __restrict__ imgs,
                                            int b, int unit)
{
    const float4* p = (const float4*)(imgs + (size_t)b * CHW)
                    + unit * ((CHW / 4) / RBLKS) + threadIdx.x;
    float4 va = __ldg(p);
    float4 vb = __ldg(p + 256);
    float4 vc = __ldg(p + 512);
    float s = ((va.x + va.y) + (va.z + va.w))
            + ((vb.x + vb.y) + (vb.z + vb.w))
            + ((vc.x + vc.y) + (vc.z + vc.w));
    #pragma unroll
    for (int o = 16; o; o >>= 1) s += __shfl_down_sync(0xffffffffu, s, o);
    __shared__ float ss[8];
    if ((threadIdx.x & 31) == 0) ss[threadIdx.x >> 5] = s;
    __syncthreads();
    if (threadIdx.x < 8) {
        s = ss[threadIdx.x];
        #pragma unroll
        for (int o = 4; o; o >>= 1) s += __shfl_down_sync(0xffu, s, o);
        if (threadIdx.x == 0) g_part[b * RBLKS + unit] = s;
    }
    __syncthreads();   // ss safe for reuse by transform phase
}

// Elements s..s+3 of the 8-float concatenation [A|B]; s uniform per image.
__device__ __forceinline__ float4 sel4(float4 A, float4 B, int s) {
    switch (s & 3) {
    case 0:  return A;
    case 1:  return make_float4(A.y, A.z, A.w, B.x);
    case 2:  return make_float4(A.z, A.w, B.x, B.y);
    default: return make_float4(A.w, B.x, B.y, B.z);
    }
}

// ---- transform unit (partials ready): one float4/thread in 3 planes ----
// Gather = 2 aligned LDG.128 per plane (6 total), sel4 component select.
__device__ __forceinline__ void transform_unit(
    const float* __restrict__ imgs,
    const float* __restrict__ br,  const float* __restrict__ sat,
    const float* __restrict__ con, const int* __restrict__ tx,
    const int* __restrict__ ty,    const int* __restrict__ cx,
    const int* __restrict__ cy,    float* __restrict__ out,
    int b, int unit)
{
    int idx4 = unit * 256 + threadIdx.x;
    int h    = idx4 >> 6;
    int w0   = (idx4 & 63) << 2;

    __shared__ float sM0;
    if (threadIdx.x < 32) {
        float s = g_part[b * RBLKS + threadIdx.x]
                + g_part[b * RBLKS + 32 + threadIdx.x];
        #pragma unroll
        for (int o = 16; o; o >>= 1) s += __shfl_down_sync(0xffffffffu, s, o);
        if (threadIdx.x == 0) sM0 = s * (1.0f / (float)CHW);
    }
    __syncthreads();

    float a  = sat[b] * 2.0f;
    float k  = con[b] + 0.5f;
    float Af = k * a;
    float Bf = k * (1.0f - a);
    float Cf = (1.0f - k) * sM0 + (br[b] - 0.5f);

    int txs = tx[b] - SHIFT;
    int tys = ty[b] - SHIFT;
    int cxv = cx[b], cyv = cy[b];
    int xlo = max(0, cxv - 64), xhi = min(HH - 1, cxv + 63);
    int ylo = max(0, cyv - 64), yhi = min(WW - 1, cyv + 63);

    int  sh       = h + txs;
    bool rowvalid = (sh >= 0) & (sh < HH);
    bool rowcut   = (h >= xlo) & (h <= xhi);
    int  sh_c     = min(max(sh, 0), HH - 1);

    int sw0  = w0 + tys;
    int s    = sw0 & 3;
    int base = sw0 >> 2;
    int bA   = min(max(base,     0), 63);
    int bB   = min(max(base + 1, 0), 63);

    const float4* srow = (const float4*)(imgs + (size_t)b * CHW) + (size_t)sh_c * 64;

    float4 A0 = __ldcs(srow + bA),         B0 = __ldcs(srow + bB);
    float4 A1 = __ldcs(srow + HW4 + bA),   B1 = __ldcs(srow + HW4 + bB);
    float4 A2 = __ldcs(srow + 2*HW4 + bA), B2 = __ldcs(srow + 2*HW4 + bB);

    float4 v0 = sel4(A0, B0, s), v1 = sel4(A1, B1, s), v2 = sel4(A2, B2, s);
    float p0[4] = {v0.x, v0.y, v0.z, v0.w};
    float p1[4] = {v1.x, v1.y, v1.z, v1.w};
    float p2[4] = {v2.x, v2.y, v2.z, v2.w};

    float o0[4], o1[4], o2[4];
    #pragma unroll
    for (int j = 0; j < 4; j++) {
        int  w  = w0 + j;
        int  sw = sw0 + j;
        bool valid = rowvalid & (sw >= 0) & (sw < WW)
                   & !(rowcut & (w >= ylo) & (w <= yhi));
        float m  = (p0[j] + p1[j] + p2[j]) * (1.0f / 3.0f);
        float bm = fmaf(Bf, m, Cf);
        o0[j] = valid ? fmaf(Af, p0[j], bm) : 0.f;
        o1[j] = valid ? fmaf(Af, p1[j], bm) : 0.f;
        o2[j] = valid ? fmaf(Af, p2[j], bm) : 0.f;
    }

    float* dst = out + (size_t)b * CHW + (size_t)h * WW + w0;
    __stcs((float4*)(dst),          make_float4(o0[0], o0[1], o0[2], o0[3]));
    __stcs((float4*)(dst + HW),     make_float4(o1[0], o1[1], o1[2], o1[3]));
    __stcs((float4*)(dst + 2 * HW), make_float4(o2[0], o2[1], o2[2], o2[3]));
}

// Three modes, all 4096-block grids:
//   K0 (nred>0, ntr==0): pure reduce of half 0.
//   K1 (both): EVERY block fuses reduce(half1 unit) -> gridsync ->
//              transform(half0 unit). The reduce is the pre-sync prefetch
//              work, and the DRAM read/write mix is uniform for the whole
//              kernel (no write-only tail).
//   K2 (ntr>0, nred==0): transform half 1; gather loads issued BEFORE
//              gridsync (addresses don't depend on upstream), selected after.
__global__ void __launch_bounds__(256) fused_kernel(
    const float* __restrict__ imgs,
    const float* __restrict__ br,  const float* __restrict__ sat,
    const float* __restrict__ con, const int* __restrict__ tx,
    const int* __restrict__ ty,    const int* __restrict__ cx,
    const int* __restrict__ cy,    float* __restrict__ out,
    int tbase, int rbase, int nred, int ntr)
{
    cudaTriggerProgrammaticLaunchCompletion();
    int bx = blockIdx.x;

    if (nred > 0 && ntr > 0) {
        reduce_unit(imgs, rbase + bx / RBLKS, bx % RBLKS);
        cudaGridDependencySynchronize();
        transform_unit(imgs, br, sat, con, tx, ty, cx, cy, out,
                       tbase + bx / BPI, bx % BPI);
    } else if (nred > 0) {
        reduce_unit(imgs, rbase + bx / RBLKS, bx % RBLKS);
    } else {
        // K2: prefetch gathers before gridsync, then finish.
        int b    = tbase + bx / BPI;
        int unit = bx % BPI;
        int idx4 = unit * 256 + threadIdx.x;
        int h    = idx4 >> 6;
        int w0   = (idx4 & 63) << 2;

        int txs = tx[b] - SHIFT;
        int tys = ty[b] - SHIFT;
        int  sh       = h + txs;
        bool rowvalid = (sh >= 0) & (sh < HH);
        int  sh_c     = min(max(sh, 0), HH - 1);
        int sw0  = w0 + tys;
        int s    = sw0 & 3;
        int base = sw0 >> 2;
        int bA   = min(max(base,     0), 63);
        int bB   = min(max(base + 1, 0), 63);
        const float4* srow = (const float4*)(imgs + (size_t)b * CHW) + (size_t)sh_c * 64;

        float4 A0 = __ldcs(srow + bA),         B0 = __ldcs(srow + bB);
        float4 A1 = __ldcs(srow + HW4 + bA),   B1 = __ldcs(srow + HW4 + bB);
        float4 A2 = __ldcs(srow + 2*HW4 + bA), B2 = __ldcs(srow + 2*HW4 + bB);

        cudaGridDependencySynchronize();

        __shared__ float sM0;
        if (threadIdx.x < 32) {
            float t = g_part[b * RBLKS + threadIdx.x]
                    + g_part[b * RBLKS + 32 + threadIdx.x];
            #pragma unroll
            for (int o = 16; o; o >>= 1) t += __shfl_down_sync(0xffffffffu, t, o);
            if (threadIdx.x == 0) sM0 = t * (1.0f / (float)CHW);
        }
        __syncthreads();

        float aa = sat[b] * 2.0f;
        float k  = con[b] + 0.5f;
        float Af = k * aa;
        float Bf = k * (1.0f - aa);
        float Cf = (1.0f - k) * sM0 + (br[b] - 0.5f);

        int cxv = cx[b], cyv = cy[b];
        int xlo = max(0, cxv - 64), xhi = min(HH - 1, cxv + 63);
        int ylo = max(0, cyv - 64), yhi = min(WW - 1, cyv + 63);
        bool rowcut = (h >= xlo) & (h <= xhi);

        float4 v0 = sel4(A0, B0, s), v1 = sel4(A1, B1, s), v2 = sel4(A2, B2, s);
        float p0[4] = {v0.x, v0.y, v0.z, v0.w};
        float p1[4] = {v1.x, v1.y, v1.z, v1.w};
        float p2[4] = {v2.x, v2.y, v2.z, v2.w};

        float o0[4], o1[4], o2[4];
        #pragma unroll
        for (int j = 0; j < 4; j++) {
            int  w  = w0 + j;
            int  sw = sw0 + j;
            bool valid = rowvalid & (sw >= 0) & (sw < WW)
                       & !(rowcut & (w >= ylo) & (w <= yhi));
            float m  = (p0[j] + p1[j] + p2[j]) * (1.0f / 3.0f);
            float bm = fmaf(Bf, m, Cf);
            o0[j] = valid ? fmaf(Af, p0[j], bm) : 0.f;
            o1[j] = valid ? fmaf(Af, p1[j], bm) : 0.f;
            o2[j] = valid ? fmaf(Af, p2[j], bm) : 0.f;
        }

        float* dst = out + (size_t)b * CHW + (size_t)h * WW + w0;
        __stcs((float4*)(dst),          make_float4(o0[0], o0[1], o0[2], o0[3]));
        __stcs((float4*)(dst + HW),     make_float4(o1[0], o1[1], o1[2], o1[3]));
        __stcs((float4*)(dst + 2 * HW), make_float4(o2[0], o2[1], o2[2], o2[3]));
    }
}

extern "C" void kernel_launch(void* const* d_in, const int* in_sizes, int n_in,
                              void* d_out, int out_size)
{
    const float* imgs = (const float*)d_in[0];
    const float* br   = (const float*)d_in[1];
    const float* sat  = (const float*)d_in[2];
    const float* con  = (const float*)d_in[3];
    const int*   tx   = (const int*)d_in[4];
    const int*   ty   = (const int*)d_in[5];
    const int*   cx   = (const int*)d_in[6];
    const int*   cy   = (const int*)d_in[7];
    float*       out  = (float*)d_out;

    const int NB = HALF * RBLKS;   // 4096 = HALF*BPI too

    cudaLaunchAttribute attr[1];
    attr[0].id = cudaLaunchAttributeProgrammaticStreamSerialization;
    attr[0].val.programmaticStreamSerializationAllowed = 1;

    // K0: reduce half 0
    fused_kernel<<<NB, 256>>>(imgs, br, sat, con, tx, ty, cx, cy, out,
                              /*tbase*/0, /*rbase*/0, /*nred*/HALF, /*ntr*/0);
    // K1: fused reduce(half1)+transform(half0) per block (PDL)
    {
        cudaLaunchConfig_t cfg = {};
        cfg.gridDim = dim3(NB); cfg.blockDim = dim3(256);
        cfg.attrs = attr; cfg.numAttrs = 1;
        cudaLaunchKernelEx(&cfg, fused_kernel, imgs, br, sat, con, tx, ty, cx, cy, out,
                           0, HALF, HALF, HALF);
    }
    // K2: transform half 1 (PDL, prefetch before gridsync)
    {
        cudaLaunchConfig_t cfg = {};
        cfg.gridDim = dim3(NB); cfg.blockDim = dim3(256);
        cfg.attrs = attr; cfg.numAttrs = 1;
        cudaLaunchKernelEx(&cfg, fused_kernel, imgs, br, sat, con, tx, ty, cx, cy, out,
                           HALF, 0, 0, HALF);
    }
}